// round 11
// baseline (speedup 1.0000x reference)
#include <cuda_runtime.h>
#include <cuda_fp16.h>
#include <math.h>
#include <stdint.h>

#define N_TOK    65536
#define C_DIM    256
#define E_NUM    64
#define S_SLOTS  131072
#define CAPACITY 2560
#define NCHUNK   512      /* S_SLOTS / 256 (one chunk per front block) */
#define NBF      512      /* front-end blocks (128 tokens each) */

// ---------------- scratch (device globals; no allocations) ----------------
__device__ int   g_eid[S_SLOTS];
__device__ float g_sc[S_SLOTS];
__device__ int   g_pos[S_SLOTS];
__device__ int   g_hist[NCHUNK * E_NUM];
__device__ int   g_chunkbase[NCHUNK * E_NUM];
__device__ int   g_kept[E_NUM];
__device__ int   g_tok[E_NUM * CAPACITY];
__device__ __half g_ybuf[(size_t)E_NUM * CAPACITY * C_DIM];
__device__ float g_gatesum[NBF * E_NUM];
__device__ float g_load[E_NUM];
__device__ int   g_done;
// fp16 operands
__device__ __half g_xh[(size_t)N_TOK * C_DIM];
__device__ __half g_wth[(size_t)E_NUM * C_DIM * C_DIM];  // [e][n][k]

// ---------------- packed fp32x2 helpers -------------------------------------
__device__ __forceinline__ unsigned long long splat2(float x) {
    unsigned long long r;
    asm("mov.b64 %0, {%1, %1};" : "=l"(r) : "f"(x));
    return r;
}
__device__ __forceinline__ void fma2(unsigned long long& d, unsigned long long a,
                                     unsigned long long b) {
    asm("fma.rn.f32x2 %0, %1, %2, %0;" : "+l"(d) : "l"(a), "l"(b));
}
__device__ __forceinline__ float lo2(unsigned long long v) { return __uint_as_float((unsigned)v); }
__device__ __forceinline__ float hi2(unsigned long long v) { return __uint_as_float((unsigned)(v >> 32)); }

// ---------------- mma.sync / cp.async helpers (base sm_103-safe) ------------
__device__ __forceinline__ uint32_t smem_u32(const void* p) {
    uint32_t a;
    asm("{ .reg .u64 t; cvta.to.shared.u64 t, %1; cvt.u32.u64 %0, t; }"
        : "=r"(a) : "l"(p));
    return a;
}
__device__ __forceinline__ void ldsm_x4(uint32_t* r, uint32_t a) {
    asm volatile("ldmatrix.sync.aligned.m8n8.x4.shared.b16 {%0,%1,%2,%3}, [%4];"
                 : "=r"(r[0]), "=r"(r[1]), "=r"(r[2]), "=r"(r[3]) : "r"(a));
}
__device__ __forceinline__ void mma_f16(float* d, const uint32_t* a, const uint32_t* b) {
    asm volatile(
        "mma.sync.aligned.m16n8k16.row.col.f32.f16.f16.f32 "
        "{%0,%1,%2,%3}, {%4,%5,%6,%7}, {%8,%9}, {%0,%1,%2,%3};"
        : "+f"(d[0]), "+f"(d[1]), "+f"(d[2]), "+f"(d[3])
        : "r"(a[0]), "r"(a[1]), "r"(a[2]), "r"(a[3]), "r"(b[0]), "r"(b[1]));
}
__device__ __forceinline__ void cpa16(uint32_t dst, const void* src, int bytes) {
    asm volatile("cp.async.cg.shared.global [%0], [%1], 16, %2;"
                 :: "r"(dst), "l"(src), "r"(bytes));
}
#define CP_COMMIT() asm volatile("cp.async.commit_group;" ::: "memory")
#define CP_WAIT(n)  asm volatile("cp.async.wait_group %0;" :: "n"(n) : "memory")

// ---------------- K_front: convert x + logits + router + hist  (+ Wt convert)
__global__ __launch_bounds__(256, 2) void k_front(const float* __restrict__ x,
                                                  const float* __restrict__ wg,
                                                  const float* __restrict__ we) {
    __shared__ char smbuf[34816];            // overlay: tiles / logits / ts
    __shared__ float gs[8][64];
    __shared__ int h[64];

    int tid = threadIdx.x, lane = tid & 31, w = tid >> 5;
    int bx = blockIdx.x;

    if (bx >= NBF) {
        // ---- W_e convert branch: one block = one expert x 32 k-rows ----
        float (*ts)[33] = (float(*)[33])smbuf;
        int wk = bx - NBF;                   // 0..511
        int e = wk >> 3, kt0 = (wk & 7) * 32;
        int tx = tid & 31, ty = tid >> 5;    // 32 x 8
#pragma unroll 1
        for (int nt = 0; nt < 8; nt++) {
            const float* src = we + ((size_t)e * 256 + kt0) * 256 + nt * 32;
#pragma unroll
            for (int j = 0; j < 32; j += 8) ts[ty + j][tx] = src[(size_t)(ty + j) * 256 + tx];
            __syncthreads();
#pragma unroll
            for (int j = 0; j < 32; j += 8) {
                float vv = ts[tx][ty + j];
                size_t d = ((size_t)e * 256 + (size_t)nt * 32 + ty + j) * 256 + kt0 + tx;
                g_wth[d] = __float2half_rn(vv);
            }
            __syncthreads();
        }
        return;
    }

    // ---- front path ----
    float (*As)[132] = (float(*)[132])smbuf;           // 16x132 = 8448 B
    float (*Bs)[68]  = (float(*)[68])(smbuf + 8448);   // 16x68  = 4352 B
    float (*lgt)[68] = (float(*)[68])smbuf;            // 128x68 = 34816 B

    int tx = tid & 15, ty = tid >> 4;
    int row0 = bx * 128;

    if (bx == 0 && tid == 0) g_done = 0;
    if (tid < 64) h[tid] = 0;

    unsigned long long acc[8][2];
#pragma unroll
    for (int i = 0; i < 8; i++) { acc[i][0] = 0ULL; acc[i][1] = 0ULL; }

    const float4* x4 = (const float4*)x;
    const float4* w4 = (const float4*)wg;

    for (int kb = 0; kb < 16; kb++) {
        for (int l = tid; l < 512; l += 256) {
            int m = l >> 2, cs = l & 3;
            size_t gi = (size_t)(row0 + m) * 64 + kb * 4 + cs;
            float4 v = x4[gi];
            As[cs * 4 + 0][m] = v.x; As[cs * 4 + 1][m] = v.y;
            As[cs * 4 + 2][m] = v.z; As[cs * 4 + 3][m] = v.w;
            __half2 p01 = __floats2half2_rn(v.x, v.y);
            __half2 p23 = __floats2half2_rn(v.z, v.w);
            uint2 ph;
            ph.x = *(unsigned*)&p01;
            ph.y = *(unsigned*)&p23;
            ((uint2*)g_xh)[gi] = ph;
        }
        {
            int kk = tid >> 4, n4 = tid & 15;
            float4 v = w4[(size_t)(kb * 16 + kk) * 16 + n4];
            *(float4*)&Bs[kk][n4 * 4] = v;
        }
        __syncthreads();
#pragma unroll
        for (int kk = 0; kk < 16; kk++) {
            ulonglong2 bb = *(const ulonglong2*)&Bs[kk][tx * 4];
            float a[8];
            *(float4*)&a[0] = *(const float4*)&As[kk][ty * 8];
            *(float4*)&a[4] = *(const float4*)&As[kk][ty * 8 + 4];
#pragma unroll
            for (int i = 0; i < 8; i++) {
                unsigned long long s = splat2(a[i]);
                fma2(acc[i][0], s, bb.x);
                fma2(acc[i][1], s, bb.y);
            }
        }
        __syncthreads();
    }

#pragma unroll
    for (int i = 0; i < 8; i++) {
        float4 o;
        o.x = lo2(acc[i][0]); o.y = hi2(acc[i][0]);
        o.z = lo2(acc[i][1]); o.w = hi2(acc[i][1]);
        *(float4*)&lgt[ty * 8 + i][tx * 4] = o;
    }
    __syncthreads();

    float gsum_lo = 0.0f, gsum_hi = 0.0f;
    const float NEG = __int_as_float(0xff800000);
#pragma unroll 1
    for (int it = 0; it < 16; it++) {
        int t = w * 16 + it;
        float v0 = lgt[t][lane], v1 = lgt[t][lane + 32];

        float mx = fmaxf(v0, v1);
#pragma unroll
        for (int o = 16; o; o >>= 1) mx = fmaxf(mx, __shfl_xor_sync(0xffffffffu, mx, o));
        float e0 = expf(v0 - mx), e1 = expf(v1 - mx);
        float sum = e0 + e1;
#pragma unroll
        for (int o = 16; o; o >>= 1) sum += __shfl_xor_sync(0xffffffffu, sum, o);
        float g0 = e0 / sum, g1 = e1 / sum;
        gsum_lo += g0; gsum_hi += g1;

        float bv; int bi;
        if (v1 > v0) { bv = v1; bi = lane + 32; } else { bv = v0; bi = lane; }
#pragma unroll
        for (int o = 16; o; o >>= 1) {
            float ov = __shfl_xor_sync(0xffffffffu, bv, o);
            int   oi = __shfl_xor_sync(0xffffffffu, bi, o);
            if (ov > bv || (ov == bv && oi < bi)) { bv = ov; bi = oi; }
        }
        int i1 = bi;

        float w0 = (lane == i1) ? NEG : v0;
        float w1 = (lane + 32 == i1) ? NEG : v1;
        float cv; int ci;
        if (w1 > w0) { cv = w1; ci = lane + 32; } else { cv = w0; ci = lane; }
#pragma unroll
        for (int o = 16; o; o >>= 1) {
            float ov = __shfl_xor_sync(0xffffffffu, cv, o);
            int   oi = __shfl_xor_sync(0xffffffffu, ci, o);
            if (ov > cv || (ov == cv && oi < ci)) { cv = ov; ci = oi; }
        }
        int i2 = ci;

        float s1 = __shfl_sync(0xffffffffu, (i1 < 32) ? g0 : g1, i1 & 31);
        float s2 = __shfl_sync(0xffffffffu, (i2 < 32) ? g0 : g1, i2 & 31);

        if (lane == 0) {
            int tok = row0 + t;
            g_eid[2 * tok] = i1;     g_sc[2 * tok] = s1;
            g_eid[2 * tok + 1] = i2; g_sc[2 * tok + 1] = s2;
            atomicAdd(&h[i1], 1);
            atomicAdd(&h[i2], 1);
        }
    }
    gs[w][lane] = gsum_lo;
    gs[w][lane + 32] = gsum_hi;
    __syncthreads();
    if (tid < 64) {
        float s = 0.0f;
#pragma unroll
        for (int j = 0; j < 8; j++) s += gs[j][tid];
        g_gatesum[(size_t)bx * 64 + tid] = s;
        g_hist[bx * 64 + tid] = h[tid];
    }
}

// ---------------- K4: parallel exclusive scan per expert (512 chunks) -------
__global__ __launch_bounds__(512) void k_scan() {
    __shared__ int s[512];
    int e = blockIdx.x, t = threadIdx.x;
    int v = g_hist[t * 64 + e];
    s[t] = v;
    __syncthreads();
#pragma unroll
    for (int o = 1; o < 512; o <<= 1) {
        int x = (t >= o) ? s[t - o] : 0;
        __syncthreads();
        s[t] += x;
        __syncthreads();
    }
    g_chunkbase[t * 64 + e] = s[t] - v;
    if (t == 511) g_kept[e] = (s[511] < CAPACITY) ? s[511] : CAPACITY;
}

// ---------------- K5: FIFO ranks via warp ballots (256-slot chunks) ---------
__global__ __launch_bounds__(256) void k_rank() {
    __shared__ int whist[8][64];
    int t = threadIdx.x, lane = t & 31, w = t >> 5;
    int slot = blockIdx.x * 256 + t;
    int e = g_eid[slot];
    ((int*)whist)[t] = 0;
    ((int*)whist)[t + 256] = 0;
    __syncthreads();
    unsigned peers = __match_any_sync(0xffffffffu, e);
    int lr = __popc(peers & ((1u << lane) - 1u));
    if (lr == 0) whist[w][e] = __popc(peers);
    __syncthreads();
    int base = g_chunkbase[blockIdx.x * 64 + e];
    for (int j = 0; j < w; j++) base += whist[j][e];
    int rank = base + lr;
    if (rank < CAPACITY) {
        int p = e * CAPACITY + rank;
        g_pos[slot] = p;
        g_tok[p] = slot >> 1;
    } else {
        g_pos[slot] = -1;
    }
}

// ---------------- K6: grouped GEMM, fp16 HMMA, 512 thr / 32x32 warp tiles ---
// CTA: 128 gathered rows x 128 cols, K=256 in 4 chunks of 64, 2-stage cp.async.
// 16 warps, warp tile 32x32 (2 mt x 4 nt of m16n8k16) -> 32 acc regs/thread.
// __launch_bounds__(512,2) targets <=64 regs -> 2 CTAs/SM = 32 warps (2x occ).
#define TB       (128 * 144)              /* 18432 B per tile */
#define ST_A     0
#define ST_B     (TB)
#define STAGE    (2 * TB)                 /* 36864 B per stage */
#define NSTAGE   2
#define OFF_TOK  (NSTAGE * STAGE)
#define GM_SMEM  (NSTAGE * STAGE + 512)   /* 74240 B -> 2 CTAs/SM by smem */

__global__ __launch_bounds__(512, 2) void k_gemm_hmma() {
    extern __shared__ char sm[];
    const uint32_t smb = smem_u32(sm);
    int tid = threadIdx.x, lane = tid & 31, wid = tid >> 5;

    int e = blockIdx.z;
    int kept = g_kept[e];
    int m0 = blockIdx.x * 128;
    if (m0 >= kept) return;
    int n0 = blockIdx.y * 128;

    int* stok = (int*)(sm + OFF_TOK);
    if (tid < 128) {
        int r = m0 + tid;
        stok[tid] = (r < kept) ? g_tok[e * CAPACITY + r] : -1;
    }
    __syncthreads();

    const uint4* xh4 = (const uint4*)g_xh;
    const uint4* wh4 = (const uint4*)g_wth;

    // per-thread load coords: 2 (row,c8) pairs over 128x8 uint4
    int lrow[2], lc8[2];
    const uint4* asrc[2];
    const uint4* bsrc[2];
    int abytes[2];
#pragma unroll
    for (int j = 0; j < 2; j++) {
        int idx = j * 512 + tid;
        lrow[j] = idx >> 3;
        lc8[j] = idx & 7;
        int tk = stok[lrow[j]];
        int ok = tk >= 0;
        int tkc = ok ? tk : 0;
        asrc[j] = xh4 + (size_t)tkc * 32 + lc8[j];
        abytes[j] = ok ? 16 : 0;
        bsrc[j] = wh4 + (size_t)(e * 256 + n0 + lrow[j]) * 32 + lc8[j];
    }

    auto load_stage = [&](int kc, int s) {
        uint32_t sb = smb + s * STAGE;
        int koff = kc * 8;
#pragma unroll
        for (int j = 0; j < 2; j++) {
            uint32_t o = (uint32_t)(lrow[j] * 144 + lc8[j] * 16);
            cpa16(sb + ST_A + o, asrc[j] + koff, abytes[j]);
            cpa16(sb + ST_B + o, bsrc[j] + koff, 16);
        }
    };

    int wm = wid >> 2, wn = wid & 3;     // 4x4 warp grid of 32x32 tiles

    float acc[2][4][4];
#pragma unroll
    for (int mt = 0; mt < 2; mt++)
#pragma unroll
        for (int nt = 0; nt < 4; nt++)
#pragma unroll
            for (int q = 0; q < 4; q++) acc[mt][nt][q] = 0.0f;

    int a_m = lane >> 3, a_r = lane & 7;

    load_stage(0, 0);
    CP_COMMIT();

#pragma unroll
    for (int kc = 0; kc < 4; kc++) {
        if (kc < 3) {
            load_stage(kc + 1, (kc + 1) & 1);
            CP_COMMIT();
            CP_WAIT(1);
        } else {
            CP_WAIT(0);
        }
        __syncthreads();

        uint32_t base = smb + (kc & 1) * STAGE;
#pragma unroll
        for (int ks = 0; ks < 4; ks++) {
            int k0 = ks * 16;
            uint32_t ah[2][4], bh[4][2];
#pragma unroll
            for (int mt = 0; mt < 2; mt++) {
                int arow = wm * 32 + mt * 16 + (a_m & 1) * 8 + a_r;
                int acol = k0 + (a_m >> 1) * 8;
                uint32_t off = (uint32_t)(arow * 144 + acol * 2);
                ldsm_x4(ah[mt], base + ST_A + off);
            }
#pragma unroll
            for (int np = 0; np < 2; np++) {
                int brow = wn * 32 + (np * 2 + (lane >> 4)) * 8 + (lane & 7);
                int bcol = k0 + ((lane >> 3) & 1) * 8;
                uint32_t off = (uint32_t)(brow * 144 + bcol * 2);
                uint32_t r[4];
                ldsm_x4(r, base + ST_B + off);
                bh[np * 2][0] = r[0]; bh[np * 2][1] = r[1];
                bh[np * 2 + 1][0] = r[2]; bh[np * 2 + 1][1] = r[3];
            }
#pragma unroll
            for (int mt = 0; mt < 2; mt++)
#pragma unroll
                for (int nt = 0; nt < 4; nt++)
                    mma_f16(acc[mt][nt], ah[mt], bh[nt]);
        }
        __syncthreads();
    }

    // ---- epilogue: convert to fp16, stage through SMEM, coalesced stores ----
    __half* fb = (__half*)sm;                    // [128][136] halves = 34816 B
    int g = lane >> 2, c = lane & 3;
#pragma unroll
    for (int mt = 0; mt < 2; mt++) {
#pragma unroll
        for (int nt = 0; nt < 4; nt++) {
            int row = wm * 32 + mt * 16 + g;
            int col = wn * 32 + nt * 8 + c * 2;
            __half2 v0 = __floats2half2_rn(acc[mt][nt][0], acc[mt][nt][1]);
            __half2 v1 = __floats2half2_rn(acc[mt][nt][2], acc[mt][nt][3]);
            *(__half2*)&fb[row * 136 + col] = v0;
            *(__half2*)&fb[(row + 8) * 136 + col] = v1;
        }
    }
    __syncthreads();
#pragma unroll
    for (int it = 0; it < 4; it++) {
        int idx = it * 512 + tid;           // 2048 uint4 total
        int row = idx >> 4, c16 = idx & 15;
        if (m0 + row < kept) {
            uint4 v = *(const uint4*)&fb[row * 136 + c16 * 8];
            *(uint4*)(g_ybuf + ((size_t)e * CAPACITY + m0 + row) * 256 + n0 + c16 * 8) = v;
        }
    }
}

// ---------------- K_combine: fp16 ybuf, 8 outputs per thread ----------------
__global__ __launch_bounds__(256) void k_combine(float* __restrict__ out) {
    int idx = blockIdx.x * 256 + threadIdx.x;   // over N_TOK*32
    int tok = idx >> 5, c8 = idx & 31;          // 8 halves per thread
    int p0 = g_pos[2 * tok], p1 = g_pos[2 * tok + 1];
    float s0 = g_sc[2 * tok], s1 = g_sc[2 * tok + 1];
    float r[8];
#pragma unroll
    for (int j = 0; j < 8; j++) r[j] = 0.0f;
    const uint4* yb = (const uint4*)g_ybuf;
    if (p0 >= 0) {
        uint4 v = yb[(size_t)p0 * 32 + c8];
        unsigned u[4] = {v.x, v.y, v.z, v.w};
#pragma unroll
        for (int j = 0; j < 4; j++) {
            float2 f = __half22float2(*(__half2*)&u[j]);
            r[2 * j] = s0 * f.x; r[2 * j + 1] = s0 * f.y;
        }
    }
    if (p1 >= 0) {
        uint4 v = yb[(size_t)p1 * 32 + c8];
        unsigned u[4] = {v.x, v.y, v.z, v.w};
#pragma unroll
        for (int j = 0; j < 4; j++) {
            float2 f = __half22float2(*(__half2*)&u[j]);
            r[2 * j] += s1 * f.x; r[2 * j + 1] += s1 * f.y;
        }
    }
    float4* o = (float4*)(out + (size_t)tok * 256 + c8 * 8);
    o[0] = make_float4(r[0], r[1], r[2], r[3]);
    o[1] = make_float4(r[4], r[5], r[6], r[7]);
}

// ---------------- loadsum + fused aux loss ----------------------------------
__global__ __launch_bounds__(256) void k_loadsum(float* __restrict__ out, int out_size) {
    __shared__ float sh[256];
    int e = blockIdx.x;
    float s = 0.0f;
    for (int b = threadIdx.x; b < NBF; b += 256) s += g_gatesum[(size_t)b * 64 + e];
    sh[threadIdx.x] = s;
    __syncthreads();
    for (int o = 128; o; o >>= 1) {
        if (threadIdx.x < o) sh[threadIdx.x] += sh[threadIdx.x + o];
        __syncthreads();
    }
    if (threadIdx.x == 0) {
        g_load[e] = sh[0];
        __threadfence();
        if (atomicAdd(&g_done, 1) == E_NUM - 1) {
            float acc = 0.0f;
#pragma unroll 1
            for (int j = 0; j < E_NUM; j++) {
                float load = g_load[j] / (float)N_TOK;
                float d = load - (1.0f / 64.0f);
                acc += d * d;
            }
            if (out_size > N_TOK * C_DIM) out[N_TOK * C_DIM] = acc / 64.0f;
        }
    }
}

// ---------------- launch ----------------------------------------------------
extern "C" void kernel_launch(void* const* d_in, const int* in_sizes, int n_in,
                              void* d_out, int out_size) {
    const float* x  = (const float*)d_in[0];
    const float* wg = (const float*)d_in[1];
    const float* we = (const float*)d_in[2];
    float* out = (float*)d_out;

    cudaFuncSetAttribute(k_gemm_hmma, cudaFuncAttributeMaxDynamicSharedMemorySize, GM_SMEM);

    k_front     <<<2 * NBF, 256>>>(x, wg, we);
    k_scan      <<<E_NUM, 512>>>();
    k_rank      <<<NCHUNK, 256>>>();
    k_gemm_hmma <<<dim3(CAPACITY / 128, 2, E_NUM), 512, GM_SMEM>>>();
    k_combine   <<<N_TOK / 8, 256>>>(out);
    k_loadsum   <<<E_NUM, 256>>>(out, out_size);
}

// round 12
// speedup vs baseline: 1.0545x; 1.0545x over previous
#include <cuda_runtime.h>
#include <cuda_fp16.h>
#include <math.h>
#include <stdint.h>

#define N_TOK    65536
#define C_DIM    256
#define E_NUM    64
#define S_SLOTS  131072
#define CAPACITY 2560
#define NCHUNK   512      /* S_SLOTS / 256 (one chunk per front block) */
#define NBF      512      /* front-end blocks (128 tokens each) */

// ---------------- scratch (device globals; no allocations) ----------------
__device__ int   g_eid[S_SLOTS];
__device__ float g_sc[S_SLOTS];
__device__ int   g_pos[S_SLOTS];
__device__ int   g_hist[NCHUNK * E_NUM];
__device__ int   g_kept[E_NUM];
__device__ int   g_tok[E_NUM * CAPACITY];
__device__ __half g_ybuf[(size_t)E_NUM * CAPACITY * C_DIM];
__device__ float g_gatesum[NBF * E_NUM];
__device__ float g_load[E_NUM];
__device__ int   g_done;
// fp16 operands
__device__ __half g_xh[(size_t)N_TOK * C_DIM];
__device__ __half g_wth[(size_t)E_NUM * C_DIM * C_DIM];  // [e][n][k]

// ---------------- packed fp32x2 helpers -------------------------------------
__device__ __forceinline__ unsigned long long splat2(float x) {
    unsigned long long r;
    asm("mov.b64 %0, {%1, %1};" : "=l"(r) : "f"(x));
    return r;
}
__device__ __forceinline__ void fma2(unsigned long long& d, unsigned long long a,
                                     unsigned long long b) {
    asm("fma.rn.f32x2 %0, %1, %2, %0;" : "+l"(d) : "l"(a), "l"(b));
}
__device__ __forceinline__ float lo2(unsigned long long v) { return __uint_as_float((unsigned)v); }
__device__ __forceinline__ float hi2(unsigned long long v) { return __uint_as_float((unsigned)(v >> 32)); }

// ---------------- mma.sync / cp.async helpers (base sm_103-safe) ------------
__device__ __forceinline__ uint32_t smem_u32(const void* p) {
    uint32_t a;
    asm("{ .reg .u64 t; cvta.to.shared.u64 t, %1; cvt.u32.u64 %0, t; }"
        : "=r"(a) : "l"(p));
    return a;
}
__device__ __forceinline__ void ldsm_x4(uint32_t* r, uint32_t a) {
    asm volatile("ldmatrix.sync.aligned.m8n8.x4.shared.b16 {%0,%1,%2,%3}, [%4];"
                 : "=r"(r[0]), "=r"(r[1]), "=r"(r[2]), "=r"(r[3]) : "r"(a));
}
__device__ __forceinline__ void mma_f16(float* d, const uint32_t* a, const uint32_t* b) {
    asm volatile(
        "mma.sync.aligned.m16n8k16.row.col.f32.f16.f16.f32 "
        "{%0,%1,%2,%3}, {%4,%5,%6,%7}, {%8,%9}, {%0,%1,%2,%3};"
        : "+f"(d[0]), "+f"(d[1]), "+f"(d[2]), "+f"(d[3])
        : "r"(a[0]), "r"(a[1]), "r"(a[2]), "r"(a[3]), "r"(b[0]), "r"(b[1]));
}
__device__ __forceinline__ void cpa16(uint32_t dst, const void* src, int bytes) {
    asm volatile("cp.async.cg.shared.global [%0], [%1], 16, %2;"
                 :: "r"(dst), "l"(src), "r"(bytes));
}
#define CP_COMMIT() asm volatile("cp.async.commit_group;" ::: "memory")
#define CP_WAIT(n)  asm volatile("cp.async.wait_group %0;" :: "n"(n) : "memory")

// ---------------- K_front: convert x + logits + router + hist  (+ Wt convert)
__global__ __launch_bounds__(256, 2) void k_front(const float* __restrict__ x,
                                                  const float* __restrict__ wg,
                                                  const float* __restrict__ we) {
    __shared__ char smbuf[34816];            // overlay: tiles / logits / ts
    __shared__ float gs[8][64];
    __shared__ int h[64];

    int tid = threadIdx.x, lane = tid & 31, w = tid >> 5;
    int bx = blockIdx.x;

    if (bx >= NBF) {
        // ---- W_e convert branch: one block = one expert x 32 k-rows ----
        float (*ts)[33] = (float(*)[33])smbuf;
        int wk = bx - NBF;                   // 0..511
        int e = wk >> 3, kt0 = (wk & 7) * 32;
        int tx = tid & 31, ty = tid >> 5;    // 32 x 8
#pragma unroll 1
        for (int nt = 0; nt < 8; nt++) {
            const float* src = we + ((size_t)e * 256 + kt0) * 256 + nt * 32;
#pragma unroll
            for (int j = 0; j < 32; j += 8) ts[ty + j][tx] = src[(size_t)(ty + j) * 256 + tx];
            __syncthreads();
#pragma unroll
            for (int j = 0; j < 32; j += 8) {
                float vv = ts[tx][ty + j];
                size_t d = ((size_t)e * 256 + (size_t)nt * 32 + ty + j) * 256 + kt0 + tx;
                g_wth[d] = __float2half_rn(vv);
            }
            __syncthreads();
        }
        return;
    }

    // ---- front path ----
    float (*As)[132] = (float(*)[132])smbuf;           // 16x132 = 8448 B
    float (*Bs)[68]  = (float(*)[68])(smbuf + 8448);   // 16x68  = 4352 B
    float (*lgt)[68] = (float(*)[68])smbuf;            // 128x68 = 34816 B

    int tx = tid & 15, ty = tid >> 4;
    int row0 = bx * 128;

    if (bx == 0 && tid == 0) g_done = 0;
    if (tid < 64) h[tid] = 0;

    unsigned long long acc[8][2];
#pragma unroll
    for (int i = 0; i < 8; i++) { acc[i][0] = 0ULL; acc[i][1] = 0ULL; }

    const float4* x4 = (const float4*)x;
    const float4* w4 = (const float4*)wg;

    for (int kb = 0; kb < 16; kb++) {
        for (int l = tid; l < 512; l += 256) {
            int m = l >> 2, cs = l & 3;
            size_t gi = (size_t)(row0 + m) * 64 + kb * 4 + cs;
            float4 v = x4[gi];
            As[cs * 4 + 0][m] = v.x; As[cs * 4 + 1][m] = v.y;
            As[cs * 4 + 2][m] = v.z; As[cs * 4 + 3][m] = v.w;
            __half2 p01 = __floats2half2_rn(v.x, v.y);
            __half2 p23 = __floats2half2_rn(v.z, v.w);
            uint2 ph;
            ph.x = *(unsigned*)&p01;
            ph.y = *(unsigned*)&p23;
            ((uint2*)g_xh)[gi] = ph;
        }
        {
            int kk = tid >> 4, n4 = tid & 15;
            float4 v = w4[(size_t)(kb * 16 + kk) * 16 + n4];
            *(float4*)&Bs[kk][n4 * 4] = v;
        }
        __syncthreads();
#pragma unroll
        for (int kk = 0; kk < 16; kk++) {
            ulonglong2 bb = *(const ulonglong2*)&Bs[kk][tx * 4];
            float a[8];
            *(float4*)&a[0] = *(const float4*)&As[kk][ty * 8];
            *(float4*)&a[4] = *(const float4*)&As[kk][ty * 8 + 4];
#pragma unroll
            for (int i = 0; i < 8; i++) {
                unsigned long long s = splat2(a[i]);
                fma2(acc[i][0], s, bb.x);
                fma2(acc[i][1], s, bb.y);
            }
        }
        __syncthreads();
    }

#pragma unroll
    for (int i = 0; i < 8; i++) {
        float4 o;
        o.x = lo2(acc[i][0]); o.y = hi2(acc[i][0]);
        o.z = lo2(acc[i][1]); o.w = hi2(acc[i][1]);
        *(float4*)&lgt[ty * 8 + i][tx * 4] = o;
    }
    __syncthreads();

    float gsum_lo = 0.0f, gsum_hi = 0.0f;
    const float NEG = __int_as_float(0xff800000);
#pragma unroll 1
    for (int it = 0; it < 16; it++) {
        int t = w * 16 + it;
        float v0 = lgt[t][lane], v1 = lgt[t][lane + 32];

        float mx = fmaxf(v0, v1);
#pragma unroll
        for (int o = 16; o; o >>= 1) mx = fmaxf(mx, __shfl_xor_sync(0xffffffffu, mx, o));
        float e0 = expf(v0 - mx), e1 = expf(v1 - mx);
        float sum = e0 + e1;
#pragma unroll
        for (int o = 16; o; o >>= 1) sum += __shfl_xor_sync(0xffffffffu, sum, o);
        float g0 = e0 / sum, g1 = e1 / sum;
        gsum_lo += g0; gsum_hi += g1;

        float bv; int bi;
        if (v1 > v0) { bv = v1; bi = lane + 32; } else { bv = v0; bi = lane; }
#pragma unroll
        for (int o = 16; o; o >>= 1) {
            float ov = __shfl_xor_sync(0xffffffffu, bv, o);
            int   oi = __shfl_xor_sync(0xffffffffu, bi, o);
            if (ov > bv || (ov == bv && oi < bi)) { bv = ov; bi = oi; }
        }
        int i1 = bi;

        float w0 = (lane == i1) ? NEG : v0;
        float w1 = (lane + 32 == i1) ? NEG : v1;
        float cv; int ci;
        if (w1 > w0) { cv = w1; ci = lane + 32; } else { cv = w0; ci = lane; }
#pragma unroll
        for (int o = 16; o; o >>= 1) {
            float ov = __shfl_xor_sync(0xffffffffu, cv, o);
            int   oi = __shfl_xor_sync(0xffffffffu, ci, o);
            if (ov > cv || (ov == cv && oi < ci)) { cv = ov; ci = oi; }
        }
        int i2 = ci;

        float s1 = __shfl_sync(0xffffffffu, (i1 < 32) ? g0 : g1, i1 & 31);
        float s2 = __shfl_sync(0xffffffffu, (i2 < 32) ? g0 : g1, i2 & 31);

        if (lane == 0) {
            int tok = row0 + t;
            g_eid[2 * tok] = i1;     g_sc[2 * tok] = s1;
            g_eid[2 * tok + 1] = i2; g_sc[2 * tok + 1] = s2;
            atomicAdd(&h[i1], 1);
            atomicAdd(&h[i2], 1);
        }
    }
    gs[w][lane] = gsum_lo;
    gs[w][lane + 32] = gsum_hi;
    __syncthreads();
    if (tid < 64) {
        float s = 0.0f;
#pragma unroll
        for (int j = 0; j < 8; j++) s += gs[j][tid];
        g_gatesum[(size_t)bx * 64 + tid] = s;
        g_hist[bx * 64 + tid] = h[tid];
    }
}

// ---------------- K_rank: fused exclusive-scan + FIFO ranks -----------------
// Each block (one 256-slot chunk) computes its own per-expert base by summing
// prior chunk histograms (L2-resident), then warp-ballot ranks. Last chunk
// also publishes g_kept.
__global__ __launch_bounds__(256) void k_rank() {
    __shared__ int whist[8][64];
    __shared__ int sbase[64];
    int t = threadIdx.x, lane = t & 31, w = t >> 5;
    int b = blockIdx.x;

    if (t < 64) sbase[t] = 0;
    ((int*)whist)[t] = 0;
    ((int*)whist)[t + 256] = 0;
    __syncthreads();

    // partial sums: expert = t&63, part = t>>6 strides chunks by 4
    {
        int e = t & 63, part = t >> 6;
        int s = 0;
        for (int c = part; c < b; c += 4) s += g_hist[c * 64 + e];
        atomicAdd(&sbase[e], s);
    }

    int slot = b * 256 + t;
    int e = g_eid[slot];
    unsigned peers = __match_any_sync(0xffffffffu, e);
    int lr = __popc(peers & ((1u << lane) - 1u));
    if (lr == 0) whist[w][e] = __popc(peers);
    __syncthreads();

    int base = sbase[e];
    for (int j = 0; j < w; j++) base += whist[j][e];
    int rank = base + lr;
    if (rank < CAPACITY) {
        int p = e * CAPACITY + rank;
        g_pos[slot] = p;
        g_tok[p] = slot >> 1;
    } else {
        g_pos[slot] = -1;
    }

    // last chunk publishes totals -> g_kept
    if (b == NCHUNK - 1 && t < 64) {
        int total = sbase[t] + g_hist[(NCHUNK - 1) * 64 + t];
        g_kept[t] = (total < CAPACITY) ? total : CAPACITY;
    }
}

// ---------------- K6: grouped GEMM, fp16 HMMA, cp.async 2-stage (r10) -------
#define TB       (128 * 144)              /* 18432 B per tile */
#define ST_A     0
#define ST_B     (TB)
#define STAGE    (2 * TB)                 /* 36864 B per stage */
#define NSTAGE   2
#define OFF_TOK  (NSTAGE * STAGE)
#define GM_SMEM  (NSTAGE * STAGE + 512)   /* 74240 B */

__global__ __launch_bounds__(256, 2) void k_gemm_hmma() {
    extern __shared__ char sm[];
    const uint32_t smb = smem_u32(sm);
    int tid = threadIdx.x, lane = tid & 31, wid = tid >> 5;

    int e = blockIdx.z;
    int kept = g_kept[e];
    int m0 = blockIdx.x * 128;
    if (m0 >= kept) return;
    int n0 = blockIdx.y * 128;

    int* stok = (int*)(sm + OFF_TOK);
    if (tid < 128) {
        int r = m0 + tid;
        stok[tid] = (r < kept) ? g_tok[e * CAPACITY + r] : -1;
    }
    __syncthreads();

    const uint4* xh4 = (const uint4*)g_xh;
    const uint4* wh4 = (const uint4*)g_wth;

    int lrow[4], lc8[4];
    const uint4* asrc[4];
    const uint4* bsrc[4];
    int abytes[4];
#pragma unroll
    for (int j = 0; j < 4; j++) {
        int idx = j * 256 + tid;
        lrow[j] = idx >> 3;
        lc8[j] = idx & 7;
        int tk = stok[lrow[j]];
        int ok = tk >= 0;
        int tkc = ok ? tk : 0;
        asrc[j] = xh4 + (size_t)tkc * 32 + lc8[j];
        abytes[j] = ok ? 16 : 0;
        bsrc[j] = wh4 + (size_t)(e * 256 + n0 + lrow[j]) * 32 + lc8[j];
    }

    auto load_stage = [&](int kc, int s) {
        uint32_t sb = smb + s * STAGE;
        int koff = kc * 8;
#pragma unroll
        for (int j = 0; j < 4; j++) {
            uint32_t o = (uint32_t)(lrow[j] * 144 + lc8[j] * 16);
            cpa16(sb + ST_A + o, asrc[j] + koff, abytes[j]);
            cpa16(sb + ST_B + o, bsrc[j] + koff, 16);
        }
    };

    int wm = wid >> 2, wn = wid & 3;

    float acc[4][4][4];
#pragma unroll
    for (int mt = 0; mt < 4; mt++)
#pragma unroll
        for (int nt = 0; nt < 4; nt++)
#pragma unroll
            for (int q = 0; q < 4; q++) acc[mt][nt][q] = 0.0f;

    int a_m = lane >> 3, a_r = lane & 7;

    load_stage(0, 0);
    CP_COMMIT();

#pragma unroll
    for (int kc = 0; kc < 4; kc++) {
        if (kc < 3) {
            load_stage(kc + 1, (kc + 1) & 1);
            CP_COMMIT();
            CP_WAIT(1);
        } else {
            CP_WAIT(0);
        }
        __syncthreads();

        uint32_t base = smb + (kc & 1) * STAGE;
#pragma unroll
        for (int ks = 0; ks < 4; ks++) {
            int k0 = ks * 16;
            uint32_t ah[4][4], bh[4][2];
#pragma unroll
            for (int mt = 0; mt < 4; mt++) {
                int arow = wm * 64 + mt * 16 + (a_m & 1) * 8 + a_r;
                int acol = k0 + (a_m >> 1) * 8;
                uint32_t off = (uint32_t)(arow * 144 + acol * 2);
                ldsm_x4(ah[mt], base + ST_A + off);
            }
#pragma unroll
            for (int np = 0; np < 2; np++) {
                int brow = wn * 32 + (np * 2 + (lane >> 4)) * 8 + (lane & 7);
                int bcol = k0 + ((lane >> 3) & 1) * 8;
                uint32_t off = (uint32_t)(brow * 144 + bcol * 2);
                uint32_t r[4];
                ldsm_x4(r, base + ST_B + off);
                bh[np * 2][0] = r[0]; bh[np * 2][1] = r[1];
                bh[np * 2 + 1][0] = r[2]; bh[np * 2 + 1][1] = r[3];
            }
#pragma unroll
            for (int mt = 0; mt < 4; mt++)
#pragma unroll
                for (int nt = 0; nt < 4; nt++)
                    mma_f16(acc[mt][nt], ah[mt], bh[nt]);
        }
        __syncthreads();
    }

    // ---- epilogue: convert to fp16, stage through SMEM, coalesced stores ----
    __half* fb = (__half*)sm;                    // [128][136] halves = 34816 B
    int g = lane >> 2, c = lane & 3;
#pragma unroll
    for (int mt = 0; mt < 4; mt++) {
#pragma unroll
        for (int nt = 0; nt < 4; nt++) {
            int row = wm * 64 + mt * 16 + g;
            int col = wn * 32 + nt * 8 + c * 2;
            __half2 v0 = __floats2half2_rn(acc[mt][nt][0], acc[mt][nt][1]);
            __half2 v1 = __floats2half2_rn(acc[mt][nt][2], acc[mt][nt][3]);
            *(__half2*)&fb[row * 136 + col] = v0;
            *(__half2*)&fb[(row + 8) * 136 + col] = v1;
        }
    }
    __syncthreads();
#pragma unroll
    for (int it = 0; it < 8; it++) {
        int idx = it * 256 + tid;           // 2048 uint4 total
        int row = idx >> 4, c16 = idx & 15;
        if (m0 + row < kept) {
            uint4 v = *(const uint4*)&fb[row * 136 + c16 * 8];
            *(uint4*)(g_ybuf + ((size_t)e * CAPACITY + m0 + row) * 256 + n0 + c16 * 8) = v;
        }
    }
}

// ---------------- K_combine (+ fused loadsum/aux on blocks 0..63) -----------
__global__ __launch_bounds__(256) void k_combine(float* __restrict__ out, int out_size) {
    int idx = blockIdx.x * 256 + threadIdx.x;   // over N_TOK*32
    int tok = idx >> 5, c8 = idx & 31;          // 8 halves per thread
    int p0 = g_pos[2 * tok], p1 = g_pos[2 * tok + 1];
    float s0 = g_sc[2 * tok], s1 = g_sc[2 * tok + 1];
    float r[8];
#pragma unroll
    for (int j = 0; j < 8; j++) r[j] = 0.0f;
    const uint4* yb = (const uint4*)g_ybuf;
    if (p0 >= 0) {
        uint4 v = yb[(size_t)p0 * 32 + c8];
        unsigned u[4] = {v.x, v.y, v.z, v.w};
#pragma unroll
        for (int j = 0; j < 4; j++) {
            float2 f = __half22float2(*(__half2*)&u[j]);
            r[2 * j] = s0 * f.x; r[2 * j + 1] = s0 * f.y;
        }
    }
    if (p1 >= 0) {
        uint4 v = yb[(size_t)p1 * 32 + c8];
        unsigned u[4] = {v.x, v.y, v.z, v.w};
#pragma unroll
        for (int j = 0; j < 4; j++) {
            float2 f = __half22float2(*(__half2*)&u[j]);
            r[2 * j] += s1 * f.x; r[2 * j + 1] += s1 * f.y;
        }
    }
    float4* o = (float4*)(out + (size_t)tok * 256 + c8 * 8);
    o[0] = make_float4(r[0], r[1], r[2], r[3]);
    o[1] = make_float4(r[4], r[5], r[6], r[7]);

    // fused per-expert gate reduction + aux (blocks 0..63)
    if (blockIdx.x < E_NUM) {
        __shared__ float sh[256];
        int e = blockIdx.x;
        float s = 0.0f;
        for (int b = threadIdx.x; b < NBF; b += 256) s += g_gatesum[(size_t)b * 64 + e];
        sh[threadIdx.x] = s;
        __syncthreads();
        for (int o2 = 128; o2; o2 >>= 1) {
            if (threadIdx.x < o2) sh[threadIdx.x] += sh[threadIdx.x + o2];
            __syncthreads();
        }
        if (threadIdx.x == 0) {
            g_load[e] = sh[0];
            __threadfence();
            if (atomicAdd(&g_done, 1) == E_NUM - 1) {
                float acc = 0.0f;
#pragma unroll 1
                for (int j = 0; j < E_NUM; j++) {
                    float load = g_load[j] / (float)N_TOK;
                    float d = load - (1.0f / 64.0f);
                    acc += d * d;
                }
                if (out_size > N_TOK * C_DIM) out[N_TOK * C_DIM] = acc / 64.0f;
            }
        }
    }
}

// ---------------- launch ----------------------------------------------------
extern "C" void kernel_launch(void* const* d_in, const int* in_sizes, int n_in,
                              void* d_out, int out_size) {
    const float* x  = (const float*)d_in[0];
    const float* wg = (const float*)d_in[1];
    const float* we = (const float*)d_in[2];
    float* out = (float*)d_out;

    cudaFuncSetAttribute(k_gemm_hmma, cudaFuncAttributeMaxDynamicSharedMemorySize, GM_SMEM);

    k_front     <<<2 * NBF, 256>>>(x, wg, we);
    k_rank      <<<NCHUNK, 256>>>();
    k_gemm_hmma <<<dim3(CAPACITY / 128, 2, E_NUM), 256, GM_SMEM>>>();
    k_combine   <<<N_TOK / 8, 256>>>(out, out_size);
}